// round 12
// baseline (speedup 1.0000x reference)
#include <cuda_runtime.h>

// AdaptiveMemory: out[row] = cM * mem[vids[row]] + cH * h_last[row]
//   alpha = sigmoid(dot(h_last[row], W_alpha) + b_alpha)
//   cM = d + (1-d)*alpha ; cH = (1-d)*(1-alpha)
// B = 4096 rows, D = 1024.
//
// Champion structure (warp per row, 128-thread CTAs, grid 1024, default
// cache policy, deferred mem loads) upgraded to Blackwell 256-bit vector
// memory ops (ld/st.global.v8.f32): halves LSU instruction count per byte.
// Lane i owns bytes [32i, 32i+32) of each 1KB chunk -> fully coalesced,
// 32B-aligned (rows are 4KB aligned).

#define D_DIM    1024
#define CHUNKS8  4           // (D/8) / 32 lanes
#define THREADS  128         // 4 warps = 4 rows per block

__device__ __forceinline__ void ldg256(const float* p, float r[8]) {
    asm volatile("ld.global.v8.f32 {%0,%1,%2,%3,%4,%5,%6,%7}, [%8];"
                 : "=f"(r[0]), "=f"(r[1]), "=f"(r[2]), "=f"(r[3]),
                   "=f"(r[4]), "=f"(r[5]), "=f"(r[6]), "=f"(r[7])
                 : "l"(p));
}

__device__ __forceinline__ void stg256(float* p, const float r[8]) {
    asm volatile("st.global.v8.f32 [%0], {%1,%2,%3,%4,%5,%6,%7,%8};"
                 :: "l"(p),
                    "f"(r[0]), "f"(r[1]), "f"(r[2]), "f"(r[3]),
                    "f"(r[4]), "f"(r[5]), "f"(r[6]), "f"(r[7])
                 : "memory");
}

__global__ __launch_bounds__(THREADS, 8)
void adaptive_memory_kernel(const float* __restrict__ h_last,
                            const int* __restrict__ vids,
                            const float* __restrict__ mem,
                            const float* __restrict__ W_alpha,
                            const float* __restrict__ b_alpha,
                            const float* __restrict__ medium_decay,
                            float* __restrict__ out,
                            int n_mem_rows) {
    const int warp = threadIdx.x >> 5;
    const int lane = threadIdx.x & 31;
    const int row  = blockIdx.x * (THREADS / 32) + warp;

    const float* hrow = h_last + (size_t)row * D_DIM;
    int vid = vids[row];
    vid = max(0, min(vid, n_mem_rows - 1));   // branchless safety clamp
    const float* mrow = mem + (size_t)vid * D_DIM;
    float*       orow = out + (size_t)row * D_DIM;

    // h chunks persist (needed for both dot and blend): 32 regs.
    float hv[CHUNKS8][8];
    #pragma unroll
    for (int j = 0; j < CHUNKS8; j++)
        ldg256(hrow + j * 256 + lane * 8, hv[j]);

    // Dot with W (L1/L2 resident after first wave). wv is transient.
    float p = 0.0f;
    #pragma unroll
    for (int j = 0; j < CHUNKS8; j++) {
        float wv[8];
        ldg256(W_alpha + j * 256 + lane * 8, wv);
        #pragma unroll
        for (int k = 0; k < 8; k++)
            p += hv[j][k] * wv[k];
    }

    // Butterfly reduce: every lane ends with the full sum.
    #pragma unroll
    for (int off = 16; off > 0; off >>= 1)
        p += __shfl_xor_sync(0xFFFFFFFFu, p, off);

    const float sum   = p + b_alpha[0];
    const float alpha = 1.0f / (1.0f + __expf(-sum));
    const float d     = medium_decay[0];
    const float cM    = d + (1.0f - d) * alpha;
    const float cH    = (1.0f - d) * (1.0f - alpha);

    // Epilogue: mem chunks loaded here, consumed immediately.
    #pragma unroll
    for (int j = 0; j < CHUNKS8; j++) {
        float mv[8], o[8];
        ldg256(mrow + j * 256 + lane * 8, mv);
        #pragma unroll
        for (int k = 0; k < 8; k++)
            o[k] = cM * mv[k] + cH * hv[j][k];
        stg256(orow + j * 256 + lane * 8, o);
    }
}

extern "C" void kernel_launch(void* const* d_in, const int* in_sizes, int n_in,
                              void* d_out, int out_size) {
    const float* h_last       = (const float*)d_in[0];
    const int*   vids         = (const int*)d_in[1];
    const float* mem          = (const float*)d_in[2];
    const float* W_alpha      = (const float*)d_in[3];
    const float* b_alpha      = (const float*)d_in[4];
    const float* medium_decay = (const float*)d_in[5];
    float*       out          = (float*)d_out;

    const int B          = in_sizes[0] / D_DIM;  // 4096
    const int n_mem_rows = in_sizes[2] / D_DIM;  // 100000

    const int rows_per_block = THREADS / 32;     // 4
    adaptive_memory_kernel<<<B / rows_per_block, THREADS>>>(
        h_last, vids, mem, W_alpha, b_alpha, medium_decay, out, n_mem_rows);
}

// round 13
// speedup vs baseline: 1.0257x; 1.0257x over previous
#include <cuda_runtime.h>

// AdaptiveMemory: out[row] = coefM * mem[vids[row]] + coefH * h_last[row]
//   alpha = sigmoid(dot(h_last[row], W_alpha) + b_alpha)
//   coefM = d + (1-d)*alpha ; coefH = (1-d)*(1-alpha)
// B = 4096 rows, D = 1024. Warp per row; no smem, no barriers.
// 128-thread CTAs (4 rows) -> grid 1024: 6.92 CTAs/SM, 1.2% wave imbalance.
//
// FINAL (champion, R5): best of 11 structural variants. The workload is
// 48 MB of compulsory fp32 streaming traffic; at warm-L2 bandwidth plus
// per-replay fixed overhead this configuration sits on the measured floor
// (8.64 us). Occupancy (18-83%), MLP (8-32), TMA staging, kernel splitting,
// cache hints (.cg/.cs), and 256-bit vector ops were all tried; every
// deviation was neutral or regressed.

#define D_DIM   1024
#define CHUNKS  8            // (D/4) / 32 lanes
#define THREADS 128          // 4 warps = 4 rows per block

__global__ __launch_bounds__(THREADS, 8)
void adaptive_memory_kernel(const float* __restrict__ h_last,
                            const int* __restrict__ vids,
                            const float* __restrict__ mem,
                            const float* __restrict__ W_alpha,
                            const float* __restrict__ b_alpha,
                            const float* __restrict__ medium_decay,
                            float* __restrict__ out,
                            int n_mem_rows) {
    const int warp = threadIdx.x >> 5;
    const int lane = threadIdx.x & 31;
    const int row  = blockIdx.x * (THREADS / 32) + warp;

    const float4* h4 = reinterpret_cast<const float4*>(h_last + (size_t)row * D_DIM);
    const float4* w4 = reinterpret_cast<const float4*>(W_alpha);

    int vid = vids[row];
    if (vid < 0) vid = 0;
    if (vid >= n_mem_rows) vid = n_mem_rows - 1;
    const float4* m4 = reinterpret_cast<const float4*>(mem + (size_t)vid * D_DIM);

    // h chunks persist (needed for both dot and blend): 32 regs.
    float4 hv[CHUNKS];
    #pragma unroll
    for (int j = 0; j < CHUNKS; j++) hv[j] = h4[lane + 32 * j];

    // Dot with W (L1/L2 resident after first wave). wv is transient.
    float p = 0.0f;
    #pragma unroll
    for (int j = 0; j < CHUNKS; j++) {
        float4 wv = w4[lane + 32 * j];
        p += hv[j].x * wv.x + hv[j].y * wv.y + hv[j].z * wv.z + hv[j].w * wv.w;
    }

    // Butterfly reduce: every lane ends with the full sum.
    #pragma unroll
    for (int off = 16; off > 0; off >>= 1)
        p += __shfl_xor_sync(0xFFFFFFFFu, p, off);

    const float sum   = p + b_alpha[0];
    const float alpha = 1.0f / (1.0f + __expf(-sum));
    const float d     = medium_decay[0];
    const float cM    = d + (1.0f - d) * alpha;
    const float cH    = (1.0f - d) * (1.0f - alpha);

    // Epilogue: mem chunks loaded here, consumed immediately.
    float4* o4 = reinterpret_cast<float4*>(out + (size_t)row * D_DIM);
    #pragma unroll
    for (int j = 0; j < CHUNKS; j++) {
        float4 mv = m4[lane + 32 * j];
        float4 o;
        o.x = cM * mv.x + cH * hv[j].x;
        o.y = cM * mv.y + cH * hv[j].y;
        o.z = cM * mv.z + cH * hv[j].z;
        o.w = cM * mv.w + cH * hv[j].w;
        o4[lane + 32 * j] = o;
    }
}

extern "C" void kernel_launch(void* const* d_in, const int* in_sizes, int n_in,
                              void* d_out, int out_size) {
    const float* h_last       = (const float*)d_in[0];
    const int*   vids         = (const int*)d_in[1];
    const float* mem          = (const float*)d_in[2];
    const float* W_alpha      = (const float*)d_in[3];
    const float* b_alpha      = (const float*)d_in[4];
    const float* medium_decay = (const float*)d_in[5];
    float*       out          = (float*)d_out;

    const int B          = in_sizes[0] / D_DIM;  // 4096
    const int n_mem_rows = in_sizes[2] / D_DIM;  // 100000

    const int rows_per_block = THREADS / 32;     // 4
    adaptive_memory_kernel<<<B / rows_per_block, THREADS>>>(
        h_last, vids, mem, W_alpha, b_alpha, medium_decay, out, n_mem_rows);
}